// round 13
// baseline (speedup 1.0000x reference)
#include <cuda_runtime.h>
#include <stdint.h>

#define NN 100000
#define NE 1600000
#define NF 256
#define NH 64
#define NHTOT (NN * NH)          // 6,400,000
#define NCNT 100352              // 98 * 1024, padded row-counter array
#define NCH 98                   // scan chunks

// Scratch (static device globals — zero-initialized at load; each call restores
// the zero state itself so graph replays are deterministic).
__device__ __align__(16) float g_support[NHTOT];   // x @ W
__device__ __align__(16) float g_agg[NHTOT];       // segment_sum (bias cancels in BN)
__device__ int g_cnt[NCNT];                        // per-row count -> cursor -> ends
__device__ int g_loc[NCNT];                        // local exclusive scan
__device__ int g_bsum[128];
__device__ int g_bbase[128];
__device__ int g_eidx[NE];                         // edge ids bucketed by dest row
__device__ double g_sum[NH];
__device__ double g_sumsq[NH];
__device__ float g_scale[NH];
__device__ float g_shift[NH];
__device__ unsigned int g_arrive;                  // colstats completion counter

// ---------------------------------------------------------------------------
// GEMM: support[NN,64] = x[NN,256] @ W[256,64] via mma.sync tf32 (m16n8k8).
// ---------------------------------------------------------------------------
__device__ __forceinline__ float tf32r(float f) {
    uint32_t o;
    asm("cvt.rna.tf32.f32 %0, %1;" : "=r"(o) : "f"(f));
    return __uint_as_float(o);
}

__global__ __launch_bounds__(256) void k_gemm(const float* __restrict__ x,
                                              const float* __restrict__ W) {
    __shared__ float As[128][36];
    __shared__ float Bs[32][68];

    const int tid = threadIdx.x;
    const int lane = tid & 31;
    const int warp = tid >> 5;
    const int rowBase = blockIdx.x * 128;
    const int r4 = lane >> 2;
    const int c4 = lane & 3;

    float d[8][4];
#pragma unroll
    for (int n = 0; n < 8; n++)
#pragma unroll
        for (int i = 0; i < 4; i++) d[n][i] = 0.0f;

    for (int ch = 0; ch < 8; ch++) {
        const int k0 = ch * 32;
#pragma unroll
        for (int i = 0; i < 4; i++) {
            int idx = i * 256 + tid;
            int r = idx >> 3, q = idx & 7;
            float4 v = make_float4(0.f, 0.f, 0.f, 0.f);
            if (rowBase + r < NN)
                v = __ldg(reinterpret_cast<const float4*>(x + (rowBase + r) * NF + k0) + q);
            v.x = tf32r(v.x); v.y = tf32r(v.y); v.z = tf32r(v.z); v.w = tf32r(v.w);
            *reinterpret_cast<float4*>(&As[r][q * 4]) = v;
        }
#pragma unroll
        for (int i = 0; i < 2; i++) {
            int idx = i * 256 + tid;
            int r = idx >> 4, q = idx & 15;
            float4 v = __ldg(reinterpret_cast<const float4*>(W + (k0 + r) * NH) + q);
            v.x = tf32r(v.x); v.y = tf32r(v.y); v.z = tf32r(v.z); v.w = tf32r(v.w);
            *reinterpret_cast<float4*>(&Bs[r][q * 4]) = v;
        }
        __syncthreads();

        const int wr = warp * 16;
#pragma unroll
        for (int k8 = 0; k8 < 4; k8++) {
            const int kc = k8 * 8;
            uint32_t a0 = __float_as_uint(As[wr + r4][kc + c4]);
            uint32_t a1 = __float_as_uint(As[wr + r4 + 8][kc + c4]);
            uint32_t a2 = __float_as_uint(As[wr + r4][kc + c4 + 4]);
            uint32_t a3 = __float_as_uint(As[wr + r4 + 8][kc + c4 + 4]);
#pragma unroll
            for (int n = 0; n < 8; n++) {
                uint32_t b0 = __float_as_uint(Bs[kc + c4][n * 8 + r4]);
                uint32_t b1 = __float_as_uint(Bs[kc + c4 + 4][n * 8 + r4]);
                asm volatile(
                    "mma.sync.aligned.m16n8k8.row.col.f32.tf32.tf32.f32 "
                    "{%0,%1,%2,%3}, {%4,%5,%6,%7}, {%8,%9}, {%0,%1,%2,%3};"
                    : "+f"(d[n][0]), "+f"(d[n][1]), "+f"(d[n][2]), "+f"(d[n][3])
                    : "r"(a0), "r"(a1), "r"(a2), "r"(a3), "r"(b0), "r"(b1));
            }
        }
        __syncthreads();
    }

    const int wr = warp * 16;
#pragma unroll
    for (int n = 0; n < 8; n++) {
        int gr = rowBase + wr + r4;
        int col = n * 8 + 2 * c4;
        if (gr < NN)
            *reinterpret_cast<float2*>(g_support + gr * NH + col) =
                make_float2(d[n][0], d[n][1]);
        if (gr + 8 < NN)
            *reinterpret_cast<float2*>(g_support + (gr + 8) * NH + col) =
                make_float2(d[n][2], d[n][3]);
    }
}

// ---------------------------------------------------------------------------
// CSR binning pipeline (dest-row buckets), then atomic-free aggregation.
// ---------------------------------------------------------------------------
__global__ void k_hist(const int* __restrict__ row) {
    int e = blockIdx.x * blockDim.x + threadIdx.x;
    if (e < NE) atomicAdd(&g_cnt[__ldg(row + e)], 1);
}

__global__ __launch_bounds__(1024) void k_scan1() {
    __shared__ int sh[1024];
    int g = blockIdx.x * 1024 + threadIdx.x;
    int v = g_cnt[g];
    sh[threadIdx.x] = v;
    __syncthreads();
#pragma unroll
    for (int off = 1; off < 1024; off <<= 1) {
        int t = (threadIdx.x >= off) ? sh[threadIdx.x - off] : 0;
        __syncthreads();
        sh[threadIdx.x] += t;
        __syncthreads();
    }
    g_loc[g] = sh[threadIdx.x] - v;               // exclusive
    if (threadIdx.x == 1023) g_bsum[blockIdx.x] = sh[1023];
}

__global__ __launch_bounds__(128) void k_scan2() {
    __shared__ int sh[128];
    int i = threadIdx.x;
    int v = (i < NCH) ? g_bsum[i] : 0;
    sh[i] = v;
    __syncthreads();
#pragma unroll
    for (int off = 1; off < 128; off <<= 1) {
        int t = (i >= off) ? sh[i - off] : 0;
        __syncthreads();
        sh[i] += t;
        __syncthreads();
    }
    if (i < NCH) g_bbase[i] = sh[i] - v;          // exclusive
}

__global__ __launch_bounds__(1024) void k_base() {
    int g = blockIdx.x * 1024 + threadIdx.x;
    g_cnt[g] = g_loc[g] + g_bbase[blockIdx.x];    // cursor = global start
}

__global__ void k_fill(const int* __restrict__ row) {
    int e = blockIdx.x * blockDim.x + threadIdx.x;
    if (e >= NE) return;
    int pos = atomicAdd(&g_cnt[__ldg(row + e)], 1);
    g_eidx[pos] = e;
}

// 16 threads per row; accumulate in registers; single store; NO atomics.
__global__ __launch_bounds__(256) void k_agg(const int* __restrict__ col,
                                             const float* __restrict__ ew) {
    int t = blockIdx.x * blockDim.x + threadIdx.x;
    int r = t >> 4;
    if (r >= NN) return;
    int l = t & 15;
    int start = (r == 0) ? 0 : __ldg(&g_cnt[r - 1]);   // cnt[r-1] = end of r-1
    int end = __ldg(&g_cnt[r]);
    const float4* sup4 = reinterpret_cast<const float4*>(g_support);

    float4 acc = make_float4(0.f, 0.f, 0.f, 0.f);
    int e = start;
    int eid = (e < end) ? __ldg(&g_eidx[e]) : 0;
    while (e < end) {
        int c = __ldg(col + eid);
        float w = __ldg(ew + eid);
        int nid = (e + 1 < end) ? __ldg(&g_eidx[e + 1]) : 0;
        float4 v = __ldg(sup4 + c * 16 + l);
        acc.x = fmaf(w, v.x, acc.x);
        acc.y = fmaf(w, v.y, acc.y);
        acc.z = fmaf(w, v.z, acc.z);
        acc.w = fmaf(w, v.w, acc.w);
        eid = nid;
        e++;
    }
    *reinterpret_cast<float4*>(g_agg + r * 64 + l * 4) = acc;
}

// ---------------------------------------------------------------------------
// BN column stats (float4, high MLP) + fused finalize in the last block.
// ---------------------------------------------------------------------------
#define NSTAT_BLK 1184

__global__ __launch_bounds__(256) void k_colstats(const float* __restrict__ gamma,
                                                  const float* __restrict__ beta) {
    int j4 = threadIdx.x & 15;
    int grp = threadIdx.x >> 4;
    float4 s = make_float4(0.f, 0.f, 0.f, 0.f);
    float4 q = make_float4(0.f, 0.f, 0.f, 0.f);
    for (int r = blockIdx.x * 16 + grp; r < NN; r += NSTAT_BLK * 16) {
        float4 v = *reinterpret_cast<const float4*>(g_agg + r * 64 + j4 * 4);
        s.x += v.x; s.y += v.y; s.z += v.z; s.w += v.w;
        q.x = fmaf(v.x, v.x, q.x); q.y = fmaf(v.y, v.y, q.y);
        q.z = fmaf(v.z, v.z, q.z); q.w = fmaf(v.w, v.w, q.w);
    }
    __shared__ float ss[16][68], sq[16][68];
    __shared__ bool s_last;
    *reinterpret_cast<float4*>(&ss[grp][j4 * 4]) = s;
    *reinterpret_cast<float4*>(&sq[grp][j4 * 4]) = q;
    __syncthreads();
    if (threadIdx.x < 64) {
        int j = threadIdx.x;
        float S = 0.f, Q = 0.f;
#pragma unroll
        for (int g = 0; g < 16; g++) { S += ss[g][j]; Q += sq[g][j]; }
        atomicAdd(&g_sum[j], (double)S);
        atomicAdd(&g_sumsq[j], (double)Q);
    }
    __syncthreads();
    if (threadIdx.x == 0) {
        __threadfence();
        unsigned int prev = atomicAdd(&g_arrive, 1u);
        s_last = (prev == NSTAT_BLK - 1);
    }
    __syncthreads();
    if (s_last) {
        if (threadIdx.x < NH) {
            int j = threadIdx.x;
            double mean = g_sum[j] / (double)NN;
            double var = g_sumsq[j] / (double)NN - mean * mean;
            float sc = (float)((double)gamma[j] * rsqrt(var + 1e-5));
            g_scale[j] = sc;
            g_shift[j] = beta[j] - (float)mean * sc;
            g_sum[j] = 0.0;
            g_sumsq[j] = 0.0;
        }
        if (threadIdx.x == 64) g_arrive = 0u;
    }
}

// ---------------------------------------------------------------------------
// Epilogue: BN affine + ReLU + JAX threefry dropout (partitionable layout).
// 16 elements / thread (4 float4 chunks, stride 1024). Also re-zeroes g_cnt.
// ---------------------------------------------------------------------------
#define TFR4(rot)                                                   \
    _Pragma("unroll")                                               \
    for (int t = 0; t < 4; t++) {                                   \
        x0[t] += x1[t];                                             \
        x1[t] = __funnelshift_l(x1[t], x1[t], (rot));               \
        x1[t] ^= x0[t];                                             \
    }
#define TFK4(ka, kb, rconst)                                        \
    _Pragma("unroll")                                               \
    for (int t = 0; t < 4; t++) {                                   \
        x0[t] += (ka);                                              \
        x1[t] += (kb) + (rconst);                                   \
    }

__device__ __forceinline__ void tf_bits4(uint32_t base, uint32_t* bits) {
    const uint32_t ks0 = 0u, ks1 = 42u, ks2 = 0x1BD11BDAu ^ 42u;
    uint32_t x0[4], x1[4];
#pragma unroll
    for (int t = 0; t < 4; t++) {
        x0[t] = ks0;
        x1[t] = (base + (uint32_t)t) + ks1;
    }
    TFR4(13) TFR4(15) TFR4(26) TFR4(6)
    TFK4(ks1, ks2, 1u)
    TFR4(17) TFR4(29) TFR4(16) TFR4(24)
    TFK4(ks2, ks0, 2u)
    TFR4(13) TFR4(15) TFR4(26) TFR4(6)
    TFK4(ks0, ks1, 3u)
    TFR4(17) TFR4(29) TFR4(16) TFR4(24)
    TFK4(ks1, ks2, 4u)
    TFR4(13) TFR4(15) TFR4(26) TFR4(6)
    TFK4(ks2, ks0, 5u)
#pragma unroll
    for (int t = 0; t < 4; t++) bits[t] = x0[t] ^ x1[t];
}

__global__ __launch_bounds__(256) void k_out(float* __restrict__ out) {
    // restore zero state of the row counters for the next call
    int gt = blockIdx.x * 256 + threadIdx.x;
    if (gt < NCNT) g_cnt[gt] = 0;

    const int blockBase = blockIdx.x * 4096;
    const int base0 = blockBase + threadIdx.x * 4;

    float4 v[4];
    bool ok[4];
#pragma unroll
    for (int c = 0; c < 4; c++) {
        int idx = base0 + c * 1024;
        ok[c] = idx < NHTOT;
        if (ok[c]) v[c] = *reinterpret_cast<const float4*>(g_agg + idx);
    }

    const int j = base0 & 63;
    float4 sc = *reinterpret_cast<const float4*>(g_scale + j);
    float4 sh = *reinterpret_cast<const float4*>(g_shift + j);
    const float scs[4] = {sc.x, sc.y, sc.z, sc.w};
    const float shs[4] = {sh.x, sh.y, sh.z, sh.w};
    const float inv_keep = 1.0f / 0.7f;

#pragma unroll
    for (int c = 0; c < 4; c++) {
        if (!ok[c]) continue;
        int idx = base0 + c * 1024;
        uint32_t bits[4];
        tf_bits4((uint32_t)idx, bits);
        float vals[4] = {v[c].x, v[c].y, v[c].z, v[c].w};
        float res[4];
#pragma unroll
        for (int t = 0; t < 4; t++) {
            float u = __uint_as_float((bits[t] >> 9) | 0x3f800000u) - 1.0f;
            float h = fmaxf(fmaf(vals[t], scs[t], shs[t]), 0.0f);
            res[t] = (u < 0.7f) ? h * inv_keep : 0.0f;
        }
        *reinterpret_cast<float4*>(out + idx) =
            make_float4(res[0], res[1], res[2], res[3]);
    }
}

// ---------------------------------------------------------------------------
extern "C" void kernel_launch(void* const* d_in, const int* in_sizes, int n_in,
                              void* d_out, int out_size) {
    const float* x     = (const float*)d_in[0];
    const int*   row   = (const int*)d_in[1];
    const int*   col   = (const int*)d_in[2];
    const float* ew    = (const float*)d_in[3];
    const float* W     = (const float*)d_in[4];
    const float* gamma = (const float*)d_in[6];
    const float* beta  = (const float*)d_in[7];
    float* out = (float*)d_out;

    k_gemm<<<(NN + 127) / 128, 256>>>(x, W);
    k_hist<<<(NE + 255) / 256, 256>>>(row);
    k_scan1<<<NCH, 1024>>>();
    k_scan2<<<1, 128>>>();
    k_base<<<NCH, 1024>>>();
    k_fill<<<(NE + 255) / 256, 256>>>(row);
    k_agg<<<(NN * 16 + 255) / 256, 256>>>(col, ew);
    k_colstats<<<NSTAT_BLK, 256>>>(gamma, beta);
    k_out<<<(NHTOT + 4095) / 4096, 256>>>(out);
}

// round 14
// speedup vs baseline: 1.2726x; 1.2726x over previous
#include <cuda_runtime.h>
#include <stdint.h>

#define NN 100000
#define NE 1600000
#define NF 256
#define NH 64
#define NHTOT (NN * NH)          // 6,400,000
#define NCNT 100352              // 98 * 1024, padded row-counter array
#define NCH 98                   // scan chunks

// Scratch (static device globals — zero-initialized at load; each call restores
// the zero state itself so graph replays are deterministic).
__device__ __align__(16) float g_support[NHTOT];   // x @ W
__device__ __align__(16) float g_agg[NHTOT];       // segment_sum (bias cancels in BN)
__device__ int g_cnt[NCNT];                        // per-row histogram (rezeroed in k_out)
__device__ int g_loc[NCNT];                        // local excl scan -> cursor -> incl scan
__device__ int g_bsum[128];
__device__ int g_bbase[128];
__device__ __align__(8) int2 g_epay[NE];           // (col, ew) reordered by dest row
__device__ double g_sum[NH];
__device__ double g_sumsq[NH];
__device__ float g_scale[NH];
__device__ float g_shift[NH];
__device__ unsigned int g_arrive;                  // colstats completion counter

// ---------------------------------------------------------------------------
// GEMM: support[NN,64] = x[NN,256] @ W[256,64] via mma.sync tf32 (m16n8k8),
// software-pipelined: next chunk's LDGs issued before current chunk's compute.
// ---------------------------------------------------------------------------
__device__ __forceinline__ float tf32r(float f) {
    uint32_t o;
    asm("cvt.rna.tf32.f32 %0, %1;" : "=r"(o) : "f"(f));
    return __uint_as_float(o);
}

__global__ __launch_bounds__(256) void k_gemm(const float* __restrict__ x,
                                              const float* __restrict__ W) {
    __shared__ float As[128][36];   // 144B row stride (16B aligned)
    __shared__ float Bs[32][68];

    const int tid = threadIdx.x;
    const int lane = tid & 31;
    const int warp = tid >> 5;
    const int rowBase = blockIdx.x * 128;
    const int r4 = lane >> 2;
    const int c4 = lane & 3;

    // Per-thread staging mapping (fixed across chunks)
    const int ar[4] = {(0 * 256 + tid) >> 3, (1 * 256 + tid) >> 3,
                       (2 * 256 + tid) >> 3, (3 * 256 + tid) >> 3};
    const int aq = tid & 7;
    const int br[2] = {(0 * 256 + tid) >> 4, (1 * 256 + tid) >> 4};
    const int bq = tid & 15;

    float4 ra[4], rb[2];
    // Preload chunk 0
#pragma unroll
    for (int i = 0; i < 4; i++) {
        ra[i] = make_float4(0.f, 0.f, 0.f, 0.f);
        if (rowBase + ar[i] < NN)
            ra[i] = __ldg(reinterpret_cast<const float4*>(x + (rowBase + ar[i]) * NF) + aq);
    }
#pragma unroll
    for (int i = 0; i < 2; i++)
        rb[i] = __ldg(reinterpret_cast<const float4*>(W + br[i] * NH) + bq);

    float d[8][4];
#pragma unroll
    for (int n = 0; n < 8; n++)
#pragma unroll
        for (int i = 0; i < 4; i++) d[n][i] = 0.0f;

#pragma unroll 1
    for (int ch = 0; ch < 8; ch++) {
        // Stage preloaded regs to SMEM (with tf32 rounding)
#pragma unroll
        for (int i = 0; i < 4; i++) {
            float4 v = ra[i];
            v.x = tf32r(v.x); v.y = tf32r(v.y); v.z = tf32r(v.z); v.w = tf32r(v.w);
            *reinterpret_cast<float4*>(&As[ar[i]][aq * 4]) = v;
        }
#pragma unroll
        for (int i = 0; i < 2; i++) {
            float4 v = rb[i];
            v.x = tf32r(v.x); v.y = tf32r(v.y); v.z = tf32r(v.z); v.w = tf32r(v.w);
            *reinterpret_cast<float4*>(&Bs[br[i]][bq * 4]) = v;
        }
        __syncthreads();

        // Issue next chunk's loads (latency hidden behind compute below)
        if (ch < 7) {
            const int k0n = (ch + 1) * 32;
#pragma unroll
            for (int i = 0; i < 4; i++) {
                ra[i] = make_float4(0.f, 0.f, 0.f, 0.f);
                if (rowBase + ar[i] < NN)
                    ra[i] = __ldg(reinterpret_cast<const float4*>(
                                      x + (rowBase + ar[i]) * NF + k0n) + aq);
            }
#pragma unroll
            for (int i = 0; i < 2; i++)
                rb[i] = __ldg(reinterpret_cast<const float4*>(W + (k0n + br[i]) * NH) + bq);
        }

        const int wr = warp * 16;
#pragma unroll
        for (int k8 = 0; k8 < 4; k8++) {
            const int kc = k8 * 8;
            uint32_t a0 = __float_as_uint(As[wr + r4][kc + c4]);
            uint32_t a1 = __float_as_uint(As[wr + r4 + 8][kc + c4]);
            uint32_t a2 = __float_as_uint(As[wr + r4][kc + c4 + 4]);
            uint32_t a3 = __float_as_uint(As[wr + r4 + 8][kc + c4 + 4]);
#pragma unroll
            for (int n = 0; n < 8; n++) {
                uint32_t b0 = __float_as_uint(Bs[kc + c4][n * 8 + r4]);
                uint32_t b1 = __float_as_uint(Bs[kc + c4 + 4][n * 8 + r4]);
                asm volatile(
                    "mma.sync.aligned.m16n8k8.row.col.f32.tf32.tf32.f32 "
                    "{%0,%1,%2,%3}, {%4,%5,%6,%7}, {%8,%9}, {%0,%1,%2,%3};"
                    : "+f"(d[n][0]), "+f"(d[n][1]), "+f"(d[n][2]), "+f"(d[n][3])
                    : "r"(a0), "r"(a1), "r"(a2), "r"(a3), "r"(b0), "r"(b1));
            }
        }
        __syncthreads();
    }

    const int wr = warp * 16;
#pragma unroll
    for (int n = 0; n < 8; n++) {
        int gr = rowBase + wr + r4;
        int col = n * 8 + 2 * c4;
        if (gr < NN)
            *reinterpret_cast<float2*>(g_support + gr * NH + col) =
                make_float2(d[n][0], d[n][1]);
        if (gr + 8 < NN)
            *reinterpret_cast<float2*>(g_support + (gr + 8) * NH + col) =
                make_float2(d[n][2], d[n][3]);
    }
}

// ---------------------------------------------------------------------------
// CSR binning with payload reordering, then atomic-free aggregation.
// ---------------------------------------------------------------------------
__global__ void k_hist(const int* __restrict__ row) {
    int e = blockIdx.x * blockDim.x + threadIdx.x;
    if (e < NE) atomicAdd(&g_cnt[__ldg(row + e)], 1);
}

__global__ __launch_bounds__(1024) void k_scan1() {
    __shared__ int sh[1024];
    int g = blockIdx.x * 1024 + threadIdx.x;
    int v = g_cnt[g];
    sh[threadIdx.x] = v;
    __syncthreads();
#pragma unroll
    for (int off = 1; off < 1024; off <<= 1) {
        int t = (threadIdx.x >= off) ? sh[threadIdx.x - off] : 0;
        __syncthreads();
        sh[threadIdx.x] += t;
        __syncthreads();
    }
    g_loc[g] = sh[threadIdx.x] - v;               // local exclusive
    if (threadIdx.x == 1023) g_bsum[blockIdx.x] = sh[1023];
}

__global__ __launch_bounds__(128) void k_scan2() {
    __shared__ int sh[128];
    int i = threadIdx.x;
    int v = (i < NCH) ? g_bsum[i] : 0;
    sh[i] = v;
    __syncthreads();
#pragma unroll
    for (int off = 1; off < 128; off <<= 1) {
        int t = (i >= off) ? sh[i - off] : 0;
        __syncthreads();
        sh[i] += t;
        __syncthreads();
    }
    if (i < NCH) g_bbase[i] = sh[i] - v;          // chunk exclusive base
}

// Fill: bucket (col, ew) payload by dest row. Cursor = g_loc + chunk base.
__global__ void k_fill(const int* __restrict__ row, const int* __restrict__ col,
                       const float* __restrict__ ew) {
    int e = blockIdx.x * blockDim.x + threadIdx.x;
    if (e >= NE) return;
    int r = __ldg(row + e);
    int pos = atomicAdd(&g_loc[r], 1) + __ldg(&g_bbase[r >> 10]);
    g_epay[pos] = make_int2(__ldg(col + e), __float_as_int(__ldg(ew + e)));
}

// 16 threads per row; sequential payload stream; register accumulate; 1 store.
__global__ __launch_bounds__(256) void k_agg(const int* dummy) {
    int t = blockIdx.x * blockDim.x + threadIdx.x;
    int r = t >> 4;
    if (r >= NN) return;
    int l = t & 15;
    // After fill, g_loc[r] = local inclusive scan; +chunk base = global end.
    int end = __ldg(&g_loc[r]) + __ldg(&g_bbase[r >> 10]);
    int start = (r == 0) ? 0 : (__ldg(&g_loc[r - 1]) + __ldg(&g_bbase[(r - 1) >> 10]));
    const float4* sup4 = reinterpret_cast<const float4*>(g_support);

    float4 acc = make_float4(0.f, 0.f, 0.f, 0.f);
    int2 p = (start < end) ? __ldg(&g_epay[start]) : make_int2(0, 0);
    for (int e = start; e < end; e++) {
        int2 pn = (e + 1 < end) ? __ldg(&g_epay[e + 1]) : make_int2(0, 0);
        float w = __int_as_float(p.y);
        float4 v = __ldg(sup4 + p.x * 16 + l);
        acc.x = fmaf(w, v.x, acc.x);
        acc.y = fmaf(w, v.y, acc.y);
        acc.z = fmaf(w, v.z, acc.z);
        acc.w = fmaf(w, v.w, acc.w);
        p = pn;
    }
    *reinterpret_cast<float4*>(g_agg + r * 64 + l * 4) = acc;
}

// ---------------------------------------------------------------------------
// BN column stats (float4, high MLP) + fused finalize in the last block.
// ---------------------------------------------------------------------------
#define NSTAT_BLK 1184

__global__ __launch_bounds__(256) void k_colstats(const float* __restrict__ gamma,
                                                  const float* __restrict__ beta) {
    int j4 = threadIdx.x & 15;
    int grp = threadIdx.x >> 4;
    float4 s = make_float4(0.f, 0.f, 0.f, 0.f);
    float4 q = make_float4(0.f, 0.f, 0.f, 0.f);
    for (int r = blockIdx.x * 16 + grp; r < NN; r += NSTAT_BLK * 16) {
        float4 v = *reinterpret_cast<const float4*>(g_agg + r * 64 + j4 * 4);
        s.x += v.x; s.y += v.y; s.z += v.z; s.w += v.w;
        q.x = fmaf(v.x, v.x, q.x); q.y = fmaf(v.y, v.y, q.y);
        q.z = fmaf(v.z, v.z, q.z); q.w = fmaf(v.w, v.w, q.w);
    }
    __shared__ float ss[16][68], sq[16][68];
    __shared__ bool s_last;
    *reinterpret_cast<float4*>(&ss[grp][j4 * 4]) = s;
    *reinterpret_cast<float4*>(&sq[grp][j4 * 4]) = q;
    __syncthreads();
    if (threadIdx.x < 64) {
        int j = threadIdx.x;
        float S = 0.f, Q = 0.f;
#pragma unroll
        for (int g = 0; g < 16; g++) { S += ss[g][j]; Q += sq[g][j]; }
        atomicAdd(&g_sum[j], (double)S);
        atomicAdd(&g_sumsq[j], (double)Q);
    }
    __syncthreads();
    if (threadIdx.x == 0) {
        __threadfence();
        unsigned int prev = atomicAdd(&g_arrive, 1u);
        s_last = (prev == NSTAT_BLK - 1);
    }
    __syncthreads();
    if (s_last) {
        if (threadIdx.x < NH) {
            int j = threadIdx.x;
            double mean = g_sum[j] / (double)NN;
            double var = g_sumsq[j] / (double)NN - mean * mean;
            float sc = (float)((double)gamma[j] * rsqrt(var + 1e-5));
            g_scale[j] = sc;
            g_shift[j] = beta[j] - (float)mean * sc;
            g_sum[j] = 0.0;
            g_sumsq[j] = 0.0;
        }
        if (threadIdx.x == 64) g_arrive = 0u;
    }
}

// ---------------------------------------------------------------------------
// Epilogue: BN affine + ReLU + JAX threefry dropout (partitionable layout).
// 16 elements / thread (4 float4 chunks, stride 1024). Also re-zeroes g_cnt.
// ---------------------------------------------------------------------------
#define TFR4(rot)                                                   \
    _Pragma("unroll")                                               \
    for (int t = 0; t < 4; t++) {                                   \
        x0[t] += x1[t];                                             \
        x1[t] = __funnelshift_l(x1[t], x1[t], (rot));               \
        x1[t] ^= x0[t];                                             \
    }
#define TFK4(ka, kb, rconst)                                        \
    _Pragma("unroll")                                               \
    for (int t = 0; t < 4; t++) {                                   \
        x0[t] += (ka);                                              \
        x1[t] += (kb) + (rconst);                                   \
    }

__device__ __forceinline__ void tf_bits4(uint32_t base, uint32_t* bits) {
    const uint32_t ks0 = 0u, ks1 = 42u, ks2 = 0x1BD11BDAu ^ 42u;
    uint32_t x0[4], x1[4];
#pragma unroll
    for (int t = 0; t < 4; t++) {
        x0[t] = ks0;
        x1[t] = (base + (uint32_t)t) + ks1;
    }
    TFR4(13) TFR4(15) TFR4(26) TFR4(6)
    TFK4(ks1, ks2, 1u)
    TFR4(17) TFR4(29) TFR4(16) TFR4(24)
    TFK4(ks2, ks0, 2u)
    TFR4(13) TFR4(15) TFR4(26) TFR4(6)
    TFK4(ks0, ks1, 3u)
    TFR4(17) TFR4(29) TFR4(16) TFR4(24)
    TFK4(ks1, ks2, 4u)
    TFR4(13) TFR4(15) TFR4(26) TFR4(6)
    TFK4(ks2, ks0, 5u)
#pragma unroll
    for (int t = 0; t < 4; t++) bits[t] = x0[t] ^ x1[t];
}

__global__ __launch_bounds__(256) void k_out(float* __restrict__ out) {
    // restore zero state of the row histogram for the next call
    int gt = blockIdx.x * 256 + threadIdx.x;
    if (gt < NCNT) g_cnt[gt] = 0;

    const int blockBase = blockIdx.x * 4096;
    const int base0 = blockBase + threadIdx.x * 4;

    float4 v[4];
    bool ok[4];
#pragma unroll
    for (int c = 0; c < 4; c++) {
        int idx = base0 + c * 1024;
        ok[c] = idx < NHTOT;
        if (ok[c]) v[c] = *reinterpret_cast<const float4*>(g_agg + idx);
    }

    const int j = base0 & 63;
    float4 sc = *reinterpret_cast<const float4*>(g_scale + j);
    float4 sh = *reinterpret_cast<const float4*>(g_shift + j);
    const float scs[4] = {sc.x, sc.y, sc.z, sc.w};
    const float shs[4] = {sh.x, sh.y, sh.z, sh.w};
    const float inv_keep = 1.0f / 0.7f;

#pragma unroll
    for (int c = 0; c < 4; c++) {
        if (!ok[c]) continue;
        int idx = base0 + c * 1024;
        uint32_t bits[4];
        tf_bits4((uint32_t)idx, bits);
        float vals[4] = {v[c].x, v[c].y, v[c].z, v[c].w};
        float res[4];
#pragma unroll
        for (int t = 0; t < 4; t++) {
            float u = __uint_as_float((bits[t] >> 9) | 0x3f800000u) - 1.0f;
            float h = fmaxf(fmaf(vals[t], scs[t], shs[t]), 0.0f);
            res[t] = (u < 0.7f) ? h * inv_keep : 0.0f;
        }
        *reinterpret_cast<float4*>(out + idx) =
            make_float4(res[0], res[1], res[2], res[3]);
    }
}

// ---------------------------------------------------------------------------
extern "C" void kernel_launch(void* const* d_in, const int* in_sizes, int n_in,
                              void* d_out, int out_size) {
    const float* x     = (const float*)d_in[0];
    const int*   row   = (const int*)d_in[1];
    const int*   col   = (const int*)d_in[2];
    const float* ew    = (const float*)d_in[3];
    const float* W     = (const float*)d_in[4];
    const float* gamma = (const float*)d_in[6];
    const float* beta  = (const float*)d_in[7];
    float* out = (float*)d_out;

    k_gemm<<<(NN + 127) / 128, 256>>>(x, W);
    k_hist<<<(NE + 255) / 256, 256>>>(row);
    k_scan1<<<NCH, 1024>>>();
    k_scan2<<<1, 128>>>();
    k_fill<<<(NE + 255) / 256, 256>>>(row, col, ew);
    k_agg<<<(NN * 16 + 255) / 256, 256>>>(nullptr);
    k_colstats<<<NSTAT_BLK, 256>>>(gamma, beta);
    k_out<<<(NHTOT + 4095) / 4096, 256>>>(out);
}

// round 15
// speedup vs baseline: 1.3368x; 1.0505x over previous
#include <cuda_runtime.h>
#include <cuda_fp16.h>
#include <stdint.h>

#define NN 100000
#define NE 1600000
#define NF 256
#define NH 64
#define NHTOT (NN * NH)          // 6,400,000
#define NCNT 100352              // 98 * 1024, padded row-counter array
#define NCH 98                   // scan chunks

// Scratch (static device globals — zero-initialized at load; each call restores
// the zero state itself so graph replays are deterministic).
__device__ __align__(16) __half g_supH[NHTOT];     // x @ W  (fp16)
__device__ __align__(16) float g_agg[NHTOT];       // segment_sum (bias cancels in BN)
__device__ int g_cnt[NCNT];                        // per-row histogram (rezeroed in k_out)
__device__ int g_loc[NCNT];                        // local excl scan -> cursor -> incl scan
__device__ int g_bsum[128];
__device__ int g_bbase[128];
__device__ __align__(8) int2 g_epay[NE];           // (col, ew) reordered by dest row
__device__ double g_sum[NH];
__device__ double g_sumsq[NH];
__device__ float g_scale[NH];
__device__ float g_shift[NH];
__device__ unsigned int g_arrive;                  // colstats completion counter
__device__ unsigned int g_arrive2;                 // scan1 completion counter

// ---------------------------------------------------------------------------
// GEMM: support[NN,64] = x[NN,256] @ W[256,64] via mma.sync tf32 (m16n8k8),
// software-pipelined; epilogue stores fp16.
// ---------------------------------------------------------------------------
__device__ __forceinline__ float tf32r(float f) {
    uint32_t o;
    asm("cvt.rna.tf32.f32 %0, %1;" : "=r"(o) : "f"(f));
    return __uint_as_float(o);
}

__global__ __launch_bounds__(256) void k_gemm(const float* __restrict__ x,
                                              const float* __restrict__ W) {
    __shared__ float As[128][36];
    __shared__ float Bs[32][68];

    const int tid = threadIdx.x;
    const int lane = tid & 31;
    const int warp = tid >> 5;
    const int rowBase = blockIdx.x * 128;
    const int r4 = lane >> 2;
    const int c4 = lane & 3;

    const int ar[4] = {(0 * 256 + tid) >> 3, (1 * 256 + tid) >> 3,
                       (2 * 256 + tid) >> 3, (3 * 256 + tid) >> 3};
    const int aq = tid & 7;
    const int br[2] = {(0 * 256 + tid) >> 4, (1 * 256 + tid) >> 4};
    const int bq = tid & 15;

    float4 ra[4], rb[2];
#pragma unroll
    for (int i = 0; i < 4; i++) {
        ra[i] = make_float4(0.f, 0.f, 0.f, 0.f);
        if (rowBase + ar[i] < NN)
            ra[i] = __ldg(reinterpret_cast<const float4*>(x + (rowBase + ar[i]) * NF) + aq);
    }
#pragma unroll
    for (int i = 0; i < 2; i++)
        rb[i] = __ldg(reinterpret_cast<const float4*>(W + br[i] * NH) + bq);

    float d[8][4];
#pragma unroll
    for (int n = 0; n < 8; n++)
#pragma unroll
        for (int i = 0; i < 4; i++) d[n][i] = 0.0f;

#pragma unroll 1
    for (int ch = 0; ch < 8; ch++) {
#pragma unroll
        for (int i = 0; i < 4; i++) {
            float4 v = ra[i];
            v.x = tf32r(v.x); v.y = tf32r(v.y); v.z = tf32r(v.z); v.w = tf32r(v.w);
            *reinterpret_cast<float4*>(&As[ar[i]][aq * 4]) = v;
        }
#pragma unroll
        for (int i = 0; i < 2; i++) {
            float4 v = rb[i];
            v.x = tf32r(v.x); v.y = tf32r(v.y); v.z = tf32r(v.z); v.w = tf32r(v.w);
            *reinterpret_cast<float4*>(&Bs[br[i]][bq * 4]) = v;
        }
        __syncthreads();

        if (ch < 7) {
            const int k0n = (ch + 1) * 32;
#pragma unroll
            for (int i = 0; i < 4; i++) {
                ra[i] = make_float4(0.f, 0.f, 0.f, 0.f);
                if (rowBase + ar[i] < NN)
                    ra[i] = __ldg(reinterpret_cast<const float4*>(
                                      x + (rowBase + ar[i]) * NF + k0n) + aq);
            }
#pragma unroll
            for (int i = 0; i < 2; i++)
                rb[i] = __ldg(reinterpret_cast<const float4*>(W + (k0n + br[i]) * NH) + bq);
        }

        const int wr = warp * 16;
#pragma unroll
        for (int k8 = 0; k8 < 4; k8++) {
            const int kc = k8 * 8;
            uint32_t a0 = __float_as_uint(As[wr + r4][kc + c4]);
            uint32_t a1 = __float_as_uint(As[wr + r4 + 8][kc + c4]);
            uint32_t a2 = __float_as_uint(As[wr + r4][kc + c4 + 4]);
            uint32_t a3 = __float_as_uint(As[wr + r4 + 8][kc + c4 + 4]);
#pragma unroll
            for (int n = 0; n < 8; n++) {
                uint32_t b0 = __float_as_uint(Bs[kc + c4][n * 8 + r4]);
                uint32_t b1 = __float_as_uint(Bs[kc + c4 + 4][n * 8 + r4]);
                asm volatile(
                    "mma.sync.aligned.m16n8k8.row.col.f32.tf32.tf32.f32 "
                    "{%0,%1,%2,%3}, {%4,%5,%6,%7}, {%8,%9}, {%0,%1,%2,%3};"
                    : "+f"(d[n][0]), "+f"(d[n][1]), "+f"(d[n][2]), "+f"(d[n][3])
                    : "r"(a0), "r"(a1), "r"(a2), "r"(a3), "r"(b0), "r"(b1));
            }
        }
        __syncthreads();
    }

    const int wr = warp * 16;
#pragma unroll
    for (int n = 0; n < 8; n++) {
        int gr = rowBase + wr + r4;
        int col = n * 8 + 2 * c4;
        if (gr < NN) {
            __half2 h = __floats2half2_rn(d[n][0], d[n][1]);
            *reinterpret_cast<__half2*>(g_supH + gr * NH + col) = h;
        }
        if (gr + 8 < NN) {
            __half2 h = __floats2half2_rn(d[n][2], d[n][3]);
            *reinterpret_cast<__half2*>(g_supH + (gr + 8) * NH + col) = h;
        }
    }
}

// ---------------------------------------------------------------------------
// CSR binning with payload reordering, then atomic-free aggregation.
// ---------------------------------------------------------------------------
__global__ void k_hist(const int* __restrict__ row) {
    int e = blockIdx.x * blockDim.x + threadIdx.x;
    if (e < NE) atomicAdd(&g_cnt[__ldg(row + e)], 1);
}

// Local scan per 1024-chunk; LAST arriving block also scans the 98 chunk sums.
__global__ __launch_bounds__(1024) void k_scan1() {
    __shared__ int sh[1024];
    __shared__ bool s_last;
    int g = blockIdx.x * 1024 + threadIdx.x;
    int v = g_cnt[g];
    sh[threadIdx.x] = v;
    __syncthreads();
#pragma unroll
    for (int off = 1; off < 1024; off <<= 1) {
        int t = (threadIdx.x >= off) ? sh[threadIdx.x - off] : 0;
        __syncthreads();
        sh[threadIdx.x] += t;
        __syncthreads();
    }
    g_loc[g] = sh[threadIdx.x] - v;               // local exclusive
    if (threadIdx.x == 1023) g_bsum[blockIdx.x] = sh[1023];
    __syncthreads();
    if (threadIdx.x == 0) {
        __threadfence();
        unsigned int prev = atomicAdd(&g_arrive2, 1u);
        s_last = (prev == NCH - 1);
    }
    __syncthreads();
    if (s_last) {
        // scan the 98 chunk sums (threads 0..127)
        if (threadIdx.x < 128) {
            int i = threadIdx.x;
            int bv = (i < NCH) ? g_bsum[i] : 0;
            sh[i] = bv;
            __syncwarp();
        }
        __syncthreads();
        if (threadIdx.x < 128) {
            int i = threadIdx.x;
#pragma unroll
            for (int off = 1; off < 128; off <<= 1) {
                int t = (i >= off) ? sh[i - off] : 0;
                __syncthreads();
                sh[i] += t;
                __syncthreads();
            }
            if (i < NCH) g_bbase[i] = sh[i] - ((i < NCH) ? g_bsum[i] : 0);
            if (i == 0) g_arrive2 = 0u;
        }
    }
}

// Fill: bucket (col, ew) payload by dest row. Cursor = g_loc + chunk base.
__global__ void k_fill(const int* __restrict__ row, const int* __restrict__ col,
                       const float* __restrict__ ew) {
    int e = blockIdx.x * blockDim.x + threadIdx.x;
    if (e >= NE) return;
    int r = __ldg(row + e);
    int pos = atomicAdd(&g_loc[r], 1) + __ldg(&g_bbase[r >> 10]);
    g_epay[pos] = make_int2(__ldg(col + e), __float_as_int(__ldg(ew + e)));
}

// 8 threads per row (fp16 support: 128B row = 8 x LDG.128); register acc; 1 store.
__global__ __launch_bounds__(256) void k_agg(const int* dummy) {
    int t = blockIdx.x * blockDim.x + threadIdx.x;
    int r = t >> 3;
    if (r >= NN) return;
    int l = t & 7;
    int end = __ldg(&g_loc[r]) + __ldg(&g_bbase[r >> 10]);
    int start = (r == 0) ? 0 : (__ldg(&g_loc[r - 1]) + __ldg(&g_bbase[(r - 1) >> 10]));
    const float4* sup4 = reinterpret_cast<const float4*>(g_supH);  // 8 halves / float4

    float2 acc[4];
#pragma unroll
    for (int j = 0; j < 4; j++) acc[j] = make_float2(0.f, 0.f);

    int2 p = (start < end) ? __ldg(&g_epay[start]) : make_int2(0, 0);
    for (int e = start; e < end; e++) {
        int2 pn = (e + 1 < end) ? __ldg(&g_epay[e + 1]) : make_int2(0, 0);
        float w = __int_as_float(p.y);
        float4 raw = __ldg(sup4 + p.x * 8 + l);
        const __half2* h = reinterpret_cast<const __half2*>(&raw);
#pragma unroll
        for (int j = 0; j < 4; j++) {
            float2 f = __half22float2(h[j]);
            acc[j].x = fmaf(w, f.x, acc[j].x);
            acc[j].y = fmaf(w, f.y, acc[j].y);
        }
        p = pn;
    }
    float* dst = g_agg + r * 64 + l * 8;
    *reinterpret_cast<float4*>(dst) = make_float4(acc[0].x, acc[0].y, acc[1].x, acc[1].y);
    *reinterpret_cast<float4*>(dst + 4) = make_float4(acc[2].x, acc[2].y, acc[3].x, acc[3].y);
}

// ---------------------------------------------------------------------------
// BN column stats (float4, high MLP) + fused finalize in the last block.
// ---------------------------------------------------------------------------
#define NSTAT_BLK 1184

__global__ __launch_bounds__(256) void k_colstats(const float* __restrict__ gamma,
                                                  const float* __restrict__ beta) {
    int j4 = threadIdx.x & 15;
    int grp = threadIdx.x >> 4;
    float4 s = make_float4(0.f, 0.f, 0.f, 0.f);
    float4 q = make_float4(0.f, 0.f, 0.f, 0.f);
    for (int r = blockIdx.x * 16 + grp; r < NN; r += NSTAT_BLK * 16) {
        float4 v = *reinterpret_cast<const float4*>(g_agg + r * 64 + j4 * 4);
        s.x += v.x; s.y += v.y; s.z += v.z; s.w += v.w;
        q.x = fmaf(v.x, v.x, q.x); q.y = fmaf(v.y, v.y, q.y);
        q.z = fmaf(v.z, v.z, q.z); q.w = fmaf(v.w, v.w, q.w);
    }
    __shared__ float ss[16][68], sq[16][68];
    __shared__ bool s_last;
    *reinterpret_cast<float4*>(&ss[grp][j4 * 4]) = s;
    *reinterpret_cast<float4*>(&sq[grp][j4 * 4]) = q;
    __syncthreads();
    if (threadIdx.x < 64) {
        int j = threadIdx.x;
        float S = 0.f, Q = 0.f;
#pragma unroll
        for (int g = 0; g < 16; g++) { S += ss[g][j]; Q += sq[g][j]; }
        atomicAdd(&g_sum[j], (double)S);
        atomicAdd(&g_sumsq[j], (double)Q);
    }
    __syncthreads();
    if (threadIdx.x == 0) {
        __threadfence();
        unsigned int prev = atomicAdd(&g_arrive, 1u);
        s_last = (prev == NSTAT_BLK - 1);
    }
    __syncthreads();
    if (s_last) {
        if (threadIdx.x < NH) {
            int j = threadIdx.x;
            double mean = g_sum[j] / (double)NN;
            double var = g_sumsq[j] / (double)NN - mean * mean;
            float sc = (float)((double)gamma[j] * rsqrt(var + 1e-5));
            g_scale[j] = sc;
            g_shift[j] = beta[j] - (float)mean * sc;
            g_sum[j] = 0.0;
            g_sumsq[j] = 0.0;
        }
        if (threadIdx.x == 64) g_arrive = 0u;
    }
}

// ---------------------------------------------------------------------------
// Epilogue: BN affine + ReLU + JAX threefry dropout (partitionable layout).
// 16 elements / thread (4 float4 chunks, stride 1024). Also re-zeroes g_cnt.
// ---------------------------------------------------------------------------
#define TFR4(rot)                                                   \
    _Pragma("unroll")                                               \
    for (int t = 0; t < 4; t++) {                                   \
        x0[t] += x1[t];                                             \
        x1[t] = __funnelshift_l(x1[t], x1[t], (rot));               \
        x1[t] ^= x0[t];                                             \
    }
#define TFK4(ka, kb, rconst)                                        \
    _Pragma("unroll")                                               \
    for (int t = 0; t < 4; t++) {                                   \
        x0[t] += (ka);                                              \
        x1[t] += (kb) + (rconst);                                   \
    }

__device__ __forceinline__ void tf_bits4(uint32_t base, uint32_t* bits) {
    const uint32_t ks0 = 0u, ks1 = 42u, ks2 = 0x1BD11BDAu ^ 42u;
    uint32_t x0[4], x1[4];
#pragma unroll
    for (int t = 0; t < 4; t++) {
        x0[t] = ks0;
        x1[t] = (base + (uint32_t)t) + ks1;
    }
    TFR4(13) TFR4(15) TFR4(26) TFR4(6)
    TFK4(ks1, ks2, 1u)
    TFR4(17) TFR4(29) TFR4(16) TFR4(24)
    TFK4(ks2, ks0, 2u)
    TFR4(13) TFR4(15) TFR4(26) TFR4(6)
    TFK4(ks0, ks1, 3u)
    TFR4(17) TFR4(29) TFR4(16) TFR4(24)
    TFK4(ks1, ks2, 4u)
    TFR4(13) TFR4(15) TFR4(26) TFR4(6)
    TFK4(ks2, ks0, 5u)
#pragma unroll
    for (int t = 0; t < 4; t++) bits[t] = x0[t] ^ x1[t];
}

__global__ __launch_bounds__(256) void k_out(float* __restrict__ out) {
    // restore zero state of the row histogram for the next call
    int gt = blockIdx.x * 256 + threadIdx.x;
    if (gt < NCNT) g_cnt[gt] = 0;

    const int blockBase = blockIdx.x * 4096;
    const int base0 = blockBase + threadIdx.x * 4;

    float4 v[4];
    bool ok[4];
#pragma unroll
    for (int c = 0; c < 4; c++) {
        int idx = base0 + c * 1024;
        ok[c] = idx < NHTOT;
        if (ok[c]) v[c] = *reinterpret_cast<const float4*>(g_agg + idx);
    }

    const int j = base0 & 63;
    float4 sc = *reinterpret_cast<const float4*>(g_scale + j);
    float4 sh = *reinterpret_cast<const float4*>(g_shift + j);
    const float scs[4] = {sc.x, sc.y, sc.z, sc.w};
    const float shs[4] = {sh.x, sh.y, sh.z, sh.w};
    const float inv_keep = 1.0f / 0.7f;

#pragma unroll
    for (int c = 0; c < 4; c++) {
        if (!ok[c]) continue;
        int idx = base0 + c * 1024;
        uint32_t bits[4];
        tf_bits4((uint32_t)idx, bits);
        float vals[4] = {v[c].x, v[c].y, v[c].z, v[c].w};
        float res[4];
#pragma unroll
        for (int t = 0; t < 4; t++) {
            float u = __uint_as_float((bits[t] >> 9) | 0x3f800000u) - 1.0f;
            float h = fmaxf(fmaf(vals[t], scs[t], shs[t]), 0.0f);
            res[t] = (u < 0.7f) ? h * inv_keep : 0.0f;
        }
        *reinterpret_cast<float4*>(out + idx) =
            make_float4(res[0], res[1], res[2], res[3]);
    }
}

// ---------------------------------------------------------------------------
extern "C" void kernel_launch(void* const* d_in, const int* in_sizes, int n_in,
                              void* d_out, int out_size) {
    const float* x     = (const float*)d_in[0];
    const int*   row   = (const int*)d_in[1];
    const int*   col   = (const int*)d_in[2];
    const float* ew    = (const float*)d_in[3];
    const float* W     = (const float*)d_in[4];
    const float* gamma = (const float*)d_in[6];
    const float* beta  = (const float*)d_in[7];
    float* out = (float*)d_out;

    k_gemm<<<(NN + 127) / 128, 256>>>(x, W);
    k_hist<<<(NE + 255) / 256, 256>>>(row);
    k_scan1<<<NCH, 1024>>>();
    k_fill<<<(NE + 255) / 256, 256>>>(row, col, ew);
    k_agg<<<(NN * 8 + 255) / 256, 256>>>(nullptr);
    k_colstats<<<NSTAT_BLK, 256>>>(gamma, beta);
    k_out<<<(NHTOT + 4095) / 4096, 256>>>(out);
}

// round 16
// speedup vs baseline: 1.4023x; 1.0490x over previous
#include <cuda_runtime.h>
#include <cuda_fp16.h>
#include <stdint.h>

#define NN 100000
#define NE 1600000
#define NF 256
#define NH 64
#define NHTOT (NN * NH)          // 6,400,000
#define NCNT 100352              // 98 * 1024, padded row-counter array
#define NCH 98                   // scan chunks

// Scratch (static device globals — zero-initialized at load; each call restores
// the zero state itself so graph replays are deterministic).
__device__ __align__(16) __half g_supH[NHTOT];     // x @ W  (fp16)
__device__ __align__(16) float g_agg[NHTOT];       // segment_sum (bias cancels in BN)
__device__ int g_cnt[NCNT];                        // per-row histogram (rezeroed in k_out)
__device__ int g_loc[NCNT];                        // local excl scan -> cursor -> incl scan
__device__ int g_bsum[128];
__device__ int g_bbase[128];
__device__ __align__(8) int2 g_epay[NE];           // (col, ew) reordered by dest row
__device__ double g_sum[NH];
__device__ double g_sumsq[NH];
__device__ float g_scale[NH];
__device__ float g_shift[NH];
__device__ unsigned int g_arrive;                  // colstats completion counter
__device__ unsigned int g_arrive2;                 // scan1 completion counter

// ---------------------------------------------------------------------------
// GEMM: support[NN,64] = x[NN,256] @ W[256,64] via mma.sync tf32 (m16n8k8),
// software-pipelined; epilogue stores fp16.
// ---------------------------------------------------------------------------
__device__ __forceinline__ float tf32r(float f) {
    uint32_t o;
    asm("cvt.rna.tf32.f32 %0, %1;" : "=r"(o) : "f"(f));
    return __uint_as_float(o);
}

__global__ __launch_bounds__(256) void k_gemm(const float* __restrict__ x,
                                              const float* __restrict__ W) {
    __shared__ float As[128][36];
    __shared__ float Bs[32][68];

    const int tid = threadIdx.x;
    const int lane = tid & 31;
    const int warp = tid >> 5;
    const int rowBase = blockIdx.x * 128;
    const int r4 = lane >> 2;
    const int c4 = lane & 3;

    const int ar[4] = {(0 * 256 + tid) >> 3, (1 * 256 + tid) >> 3,
                       (2 * 256 + tid) >> 3, (3 * 256 + tid) >> 3};
    const int aq = tid & 7;
    const int br[2] = {(0 * 256 + tid) >> 4, (1 * 256 + tid) >> 4};
    const int bq = tid & 15;

    float4 ra[4], rb[2];
#pragma unroll
    for (int i = 0; i < 4; i++) {
        ra[i] = make_float4(0.f, 0.f, 0.f, 0.f);
        if (rowBase + ar[i] < NN)
            ra[i] = __ldg(reinterpret_cast<const float4*>(x + (rowBase + ar[i]) * NF) + aq);
    }
#pragma unroll
    for (int i = 0; i < 2; i++)
        rb[i] = __ldg(reinterpret_cast<const float4*>(W + br[i] * NH) + bq);

    float d[8][4];
#pragma unroll
    for (int n = 0; n < 8; n++)
#pragma unroll
        for (int i = 0; i < 4; i++) d[n][i] = 0.0f;

#pragma unroll 1
    for (int ch = 0; ch < 8; ch++) {
#pragma unroll
        for (int i = 0; i < 4; i++) {
            float4 v = ra[i];
            v.x = tf32r(v.x); v.y = tf32r(v.y); v.z = tf32r(v.z); v.w = tf32r(v.w);
            *reinterpret_cast<float4*>(&As[ar[i]][aq * 4]) = v;
        }
#pragma unroll
        for (int i = 0; i < 2; i++) {
            float4 v = rb[i];
            v.x = tf32r(v.x); v.y = tf32r(v.y); v.z = tf32r(v.z); v.w = tf32r(v.w);
            *reinterpret_cast<float4*>(&Bs[br[i]][bq * 4]) = v;
        }
        __syncthreads();

        if (ch < 7) {
            const int k0n = (ch + 1) * 32;
#pragma unroll
            for (int i = 0; i < 4; i++) {
                ra[i] = make_float4(0.f, 0.f, 0.f, 0.f);
                if (rowBase + ar[i] < NN)
                    ra[i] = __ldg(reinterpret_cast<const float4*>(
                                      x + (rowBase + ar[i]) * NF + k0n) + aq);
            }
#pragma unroll
            for (int i = 0; i < 2; i++)
                rb[i] = __ldg(reinterpret_cast<const float4*>(W + (k0n + br[i]) * NH) + bq);
        }

        const int wr = warp * 16;
#pragma unroll
        for (int k8 = 0; k8 < 4; k8++) {
            const int kc = k8 * 8;
            uint32_t a0 = __float_as_uint(As[wr + r4][kc + c4]);
            uint32_t a1 = __float_as_uint(As[wr + r4 + 8][kc + c4]);
            uint32_t a2 = __float_as_uint(As[wr + r4][kc + c4 + 4]);
            uint32_t a3 = __float_as_uint(As[wr + r4 + 8][kc + c4 + 4]);
#pragma unroll
            for (int n = 0; n < 8; n++) {
                uint32_t b0 = __float_as_uint(Bs[kc + c4][n * 8 + r4]);
                uint32_t b1 = __float_as_uint(Bs[kc + c4 + 4][n * 8 + r4]);
                asm volatile(
                    "mma.sync.aligned.m16n8k8.row.col.f32.tf32.tf32.f32 "
                    "{%0,%1,%2,%3}, {%4,%5,%6,%7}, {%8,%9}, {%0,%1,%2,%3};"
                    : "+f"(d[n][0]), "+f"(d[n][1]), "+f"(d[n][2]), "+f"(d[n][3])
                    : "r"(a0), "r"(a1), "r"(a2), "r"(a3), "r"(b0), "r"(b1));
            }
        }
        __syncthreads();
    }

    const int wr = warp * 16;
#pragma unroll
    for (int n = 0; n < 8; n++) {
        int gr = rowBase + wr + r4;
        int col = n * 8 + 2 * c4;
        if (gr < NN) {
            __half2 h = __floats2half2_rn(d[n][0], d[n][1]);
            *reinterpret_cast<__half2*>(g_supH + gr * NH + col) = h;
        }
        if (gr + 8 < NN) {
            __half2 h = __floats2half2_rn(d[n][2], d[n][3]);
            *reinterpret_cast<__half2*>(g_supH + (gr + 8) * NH + col) = h;
        }
    }
}

// ---------------------------------------------------------------------------
// CSR binning with payload reordering, then atomic-free aggregation.
// ---------------------------------------------------------------------------
__global__ void k_hist(const int* __restrict__ row) {
    int e0 = (blockIdx.x * blockDim.x + threadIdx.x) * 4;
    if (e0 >= NE) return;
    int4 r = *reinterpret_cast<const int4*>(row + e0);
    atomicAdd(&g_cnt[r.x], 1);
    atomicAdd(&g_cnt[r.y], 1);
    atomicAdd(&g_cnt[r.z], 1);
    atomicAdd(&g_cnt[r.w], 1);
}

// Local scan per 1024-chunk; LAST arriving block also scans the 98 chunk sums.
__global__ __launch_bounds__(1024) void k_scan1() {
    __shared__ int sh[1024];
    __shared__ bool s_last;
    int g = blockIdx.x * 1024 + threadIdx.x;
    int v = g_cnt[g];
    sh[threadIdx.x] = v;
    __syncthreads();
#pragma unroll
    for (int off = 1; off < 1024; off <<= 1) {
        int t = (threadIdx.x >= off) ? sh[threadIdx.x - off] : 0;
        __syncthreads();
        sh[threadIdx.x] += t;
        __syncthreads();
    }
    g_loc[g] = sh[threadIdx.x] - v;               // local exclusive
    if (threadIdx.x == 1023) g_bsum[blockIdx.x] = sh[1023];
    __syncthreads();
    if (threadIdx.x == 0) {
        __threadfence();
        unsigned int prev = atomicAdd(&g_arrive2, 1u);
        s_last = (prev == NCH - 1);
    }
    __syncthreads();
    if (s_last) {
        if (threadIdx.x < 128) {
            int i = threadIdx.x;
            int bv = (i < NCH) ? g_bsum[i] : 0;
            sh[i] = bv;
            __syncwarp();
        }
        __syncthreads();
        if (threadIdx.x < 128) {
            int i = threadIdx.x;
#pragma unroll
            for (int off = 1; off < 128; off <<= 1) {
                int t = (i >= off) ? sh[i - off] : 0;
                __syncthreads();
                sh[i] += t;
                __syncthreads();
            }
            if (i < NCH) g_bbase[i] = sh[i] - ((i < NCH) ? g_bsum[i] : 0);
            if (i == 0) g_arrive2 = 0u;
        }
    }
}

// Fill: bucket (col, ew) payload by dest row, 4 edges/thread (MLP on atomics).
__global__ void k_fill(const int* __restrict__ row, const int* __restrict__ col,
                       const float* __restrict__ ew) {
    int e0 = (blockIdx.x * blockDim.x + threadIdx.x) * 4;
    if (e0 >= NE) return;
    int4 r = *reinterpret_cast<const int4*>(row + e0);
    int4 c = *reinterpret_cast<const int4*>(col + e0);
    float4 w = *reinterpret_cast<const float4*>(ew + e0);
    int p0 = atomicAdd(&g_loc[r.x], 1) + __ldg(&g_bbase[r.x >> 10]);
    int p1 = atomicAdd(&g_loc[r.y], 1) + __ldg(&g_bbase[r.y >> 10]);
    int p2 = atomicAdd(&g_loc[r.z], 1) + __ldg(&g_bbase[r.z >> 10]);
    int p3 = atomicAdd(&g_loc[r.w], 1) + __ldg(&g_bbase[r.w >> 10]);
    g_epay[p0] = make_int2(c.x, __float_as_int(w.x));
    g_epay[p1] = make_int2(c.y, __float_as_int(w.y));
    g_epay[p2] = make_int2(c.z, __float_as_int(w.z));
    g_epay[p3] = make_int2(c.w, __float_as_int(w.w));
}

// 8 threads per row (fp16 support: 128B row = 8 x LDG.128); register acc; 1 store.
__global__ __launch_bounds__(256) void k_agg(const int* dummy) {
    int t = blockIdx.x * blockDim.x + threadIdx.x;
    int r = t >> 3;
    if (r >= NN) return;
    int l = t & 7;
    int end = __ldg(&g_loc[r]) + __ldg(&g_bbase[r >> 10]);
    int start = (r == 0) ? 0 : (__ldg(&g_loc[r - 1]) + __ldg(&g_bbase[(r - 1) >> 10]));
    const float4* sup4 = reinterpret_cast<const float4*>(g_supH);

    float2 acc[4];
#pragma unroll
    for (int j = 0; j < 4; j++) acc[j] = make_float2(0.f, 0.f);

    int2 p = (start < end) ? __ldg(&g_epay[start]) : make_int2(0, 0);
    for (int e = start; e < end; e++) {
        int2 pn = (e + 1 < end) ? __ldg(&g_epay[e + 1]) : make_int2(0, 0);
        float w = __int_as_float(p.y);
        float4 raw = __ldg(sup4 + p.x * 8 + l);
        const __half2* h = reinterpret_cast<const __half2*>(&raw);
#pragma unroll
        for (int j = 0; j < 4; j++) {
            float2 f = __half22float2(h[j]);
            acc[j].x = fmaf(w, f.x, acc[j].x);
            acc[j].y = fmaf(w, f.y, acc[j].y);
        }
        p = pn;
    }
    float* dst = g_agg + r * 64 + l * 8;
    *reinterpret_cast<float4*>(dst) = make_float4(acc[0].x, acc[0].y, acc[1].x, acc[1].y);
    *reinterpret_cast<float4*>(dst + 4) = make_float4(acc[2].x, acc[2].y, acc[3].x, acc[3].y);
}

// ---------------------------------------------------------------------------
// BN column stats (float4, high MLP) + fused finalize in the last block.
// ---------------------------------------------------------------------------
#define NSTAT_BLK 1184

__global__ __launch_bounds__(256) void k_colstats(const float* __restrict__ gamma,
                                                  const float* __restrict__ beta) {
    int j4 = threadIdx.x & 15;
    int grp = threadIdx.x >> 4;
    float4 s = make_float4(0.f, 0.f, 0.f, 0.f);
    float4 q = make_float4(0.f, 0.f, 0.f, 0.f);
    for (int r = blockIdx.x * 16 + grp; r < NN; r += NSTAT_BLK * 16) {
        float4 v = *reinterpret_cast<const float4*>(g_agg + r * 64 + j4 * 4);
        s.x += v.x; s.y += v.y; s.z += v.z; s.w += v.w;
        q.x = fmaf(v.x, v.x, q.x); q.y = fmaf(v.y, v.y, q.y);
        q.z = fmaf(v.z, v.z, q.z); q.w = fmaf(v.w, v.w, q.w);
    }
    __shared__ float ss[16][68], sq[16][68];
    __shared__ bool s_last;
    *reinterpret_cast<float4*>(&ss[grp][j4 * 4]) = s;
    *reinterpret_cast<float4*>(&sq[grp][j4 * 4]) = q;
    __syncthreads();
    if (threadIdx.x < 64) {
        int j = threadIdx.x;
        float S = 0.f, Q = 0.f;
#pragma unroll
        for (int g = 0; g < 16; g++) { S += ss[g][j]; Q += sq[g][j]; }
        atomicAdd(&g_sum[j], (double)S);
        atomicAdd(&g_sumsq[j], (double)Q);
    }
    __syncthreads();
    if (threadIdx.x == 0) {
        __threadfence();
        unsigned int prev = atomicAdd(&g_arrive, 1u);
        s_last = (prev == NSTAT_BLK - 1);
    }
    __syncthreads();
    if (s_last) {
        if (threadIdx.x < NH) {
            int j = threadIdx.x;
            double mean = g_sum[j] / (double)NN;
            double var = g_sumsq[j] / (double)NN - mean * mean;
            float sc = (float)((double)gamma[j] * rsqrt(var + 1e-5));
            g_scale[j] = sc;
            g_shift[j] = beta[j] - (float)mean * sc;
            g_sum[j] = 0.0;
            g_sumsq[j] = 0.0;
        }
        if (threadIdx.x == 64) g_arrive = 0u;
    }
}

// ---------------------------------------------------------------------------
// Epilogue: BN affine + ReLU + JAX threefry dropout (partitionable layout).
// 16 elements / thread (4 float4 chunks, stride 1024). Also re-zeroes g_cnt.
// ---------------------------------------------------------------------------
#define TFR4(rot)                                                   \
    _Pragma("unroll")                                               \
    for (int t = 0; t < 4; t++) {                                   \
        x0[t] += x1[t];                                             \
        x1[t] = __funnelshift_l(x1[t], x1[t], (rot));               \
        x1[t] ^= x0[t];                                             \
    }
#define TFK4(ka, kb, rconst)                                        \
    _Pragma("unroll")                                               \
    for (int t = 0; t < 4; t++) {                                   \
        x0[t] += (ka);                                              \
        x1[t] += (kb) + (rconst);                                   \
    }

__device__ __forceinline__ void tf_bits4(uint32_t base, uint32_t* bits) {
    const uint32_t ks0 = 0u, ks1 = 42u, ks2 = 0x1BD11BDAu ^ 42u;
    uint32_t x0[4], x1[4];
#pragma unroll
    for (int t = 0; t < 4; t++) {
        x0[t] = ks0;
        x1[t] = (base + (uint32_t)t) + ks1;
    }
    TFR4(13) TFR4(15) TFR4(26) TFR4(6)
    TFK4(ks1, ks2, 1u)
    TFR4(17) TFR4(29) TFR4(16) TFR4(24)
    TFK4(ks2, ks0, 2u)
    TFR4(13) TFR4(15) TFR4(26) TFR4(6)
    TFK4(ks0, ks1, 3u)
    TFR4(17) TFR4(29) TFR4(16) TFR4(24)
    TFK4(ks1, ks2, 4u)
    TFR4(13) TFR4(15) TFR4(26) TFR4(6)
    TFK4(ks2, ks0, 5u)
#pragma unroll
    for (int t = 0; t < 4; t++) bits[t] = x0[t] ^ x1[t];
}

__global__ __launch_bounds__(256) void k_out(float* __restrict__ out) {
    int gt = blockIdx.x * 256 + threadIdx.x;
    if (gt < NCNT) g_cnt[gt] = 0;

    const int blockBase = blockIdx.x * 4096;
    const int base0 = blockBase + threadIdx.x * 4;

    float4 v[4];
    bool ok[4];
#pragma unroll
    for (int c = 0; c < 4; c++) {
        int idx = base0 + c * 1024;
        ok[c] = idx < NHTOT;
        if (ok[c]) v[c] = *reinterpret_cast<const float4*>(g_agg + idx);
    }

    const int j = base0 & 63;
    float4 sc = *reinterpret_cast<const float4*>(g_scale + j);
    float4 sh = *reinterpret_cast<const float4*>(g_shift + j);
    const float scs[4] = {sc.x, sc.y, sc.z, sc.w};
    const float shs[4] = {sh.x, sh.y, sh.z, sh.w};
    const float inv_keep = 1.0f / 0.7f;

#pragma unroll
    for (int c = 0; c < 4; c++) {
        if (!ok[c]) continue;
        int idx = base0 + c * 1024;
        uint32_t bits[4];
        tf_bits4((uint32_t)idx, bits);
        float vals[4] = {v[c].x, v[c].y, v[c].z, v[c].w};
        float res[4];
#pragma unroll
        for (int t = 0; t < 4; t++) {
            float u = __uint_as_float((bits[t] >> 9) | 0x3f800000u) - 1.0f;
            float h = fmaxf(fmaf(vals[t], scs[t], shs[t]), 0.0f);
            res[t] = (u < 0.7f) ? h * inv_keep : 0.0f;
        }
        *reinterpret_cast<float4*>(out + idx) =
            make_float4(res[0], res[1], res[2], res[3]);
    }
}

// ---------------------------------------------------------------------------
extern "C" void kernel_launch(void* const* d_in, const int* in_sizes, int n_in,
                              void* d_out, int out_size) {
    const float* x     = (const float*)d_in[0];
    const int*   row   = (const int*)d_in[1];
    const int*   col   = (const int*)d_in[2];
    const float* ew    = (const float*)d_in[3];
    const float* W     = (const float*)d_in[4];
    const float* gamma = (const float*)d_in[6];
    const float* beta  = (const float*)d_in[7];
    float* out = (float*)d_out;

    // Host-side resources (no device memory): created once, reused every call.
    static cudaStream_t s2 = nullptr;
    static cudaEvent_t evFork = nullptr, evJoin = nullptr;
    if (s2 == nullptr) {
        cudaStreamCreateWithFlags(&s2, cudaStreamNonBlocking);
        cudaEventCreateWithFlags(&evFork, cudaEventDisableTiming);
        cudaEventCreateWithFlags(&evJoin, cudaEventDisableTiming);
    }

    // Fork: binning chain on s2, GEMM on the main (capture) stream.
    cudaEventRecord(evFork, 0);
    cudaStreamWaitEvent(s2, evFork, 0);

    k_hist<<<(NE / 4 + 255) / 256, 256, 0, s2>>>(row);
    k_scan1<<<NCH, 1024, 0, s2>>>();
    k_fill<<<(NE / 4 + 255) / 256, 256, 0, s2>>>(row, col, ew);
    cudaEventRecord(evJoin, s2);

    k_gemm<<<(NN + 127) / 128, 256>>>(x, W);

    // Join: agg needs both support (main) and epay (s2).
    cudaStreamWaitEvent(0, evJoin, 0);
    k_agg<<<(NN * 8 + 255) / 256, 256>>>(nullptr);
    k_colstats<<<NSTAT_BLK, 256>>>(gamma, beta);
    k_out<<<(NHTOT + 4095) / 4096, 256>>>(out);
}

// round 17
// speedup vs baseline: 1.4844x; 1.0586x over previous
#include <cuda_runtime.h>
#include <cuda_fp16.h>
#include <stdint.h>

#define NN 100000
#define NE 1600000
#define NF 256
#define NH 64
#define NHTOT (NN * NH)          // 6,400,000
#define NCNT 100352              // 98 * 1024, padded row-counter array
#define NCH 98                   // scan chunks

// Scratch (static device globals — zero-initialized at load; each call restores
// the zero state itself so graph replays are deterministic).
__device__ __align__(16) __half g_supH[NHTOT];     // x @ W  (fp16)
__device__ __align__(16) float g_agg[NHTOT];       // segment_sum (bias cancels in BN)
__device__ int g_cnt[NCNT];                        // per-row histogram (rezeroed in k_out)
__device__ int g_loc[NCNT];                        // local excl scan -> cursor -> incl scan
__device__ int g_bsum[128];
__device__ int g_bbase[128];
__device__ __align__(8) int2 g_epay[NE];           // (col, ew) reordered by dest row
__device__ double g_sum[NH];
__device__ double g_sumsq[NH];
__device__ float g_scale[NH];
__device__ float g_shift[NH];
__device__ unsigned int g_arrive;                  // colstats completion counter
__device__ unsigned int g_arrive2;                 // scan1 completion counter

// ---------------------------------------------------------------------------
// GEMM: support[NN,64] = x[NN,256] @ W[256,64] via mma.sync fp16 (m16n8k16),
// software-pipelined. SMEM stride 40 halves -> conflict-free fragment LDS.32.
// ---------------------------------------------------------------------------
#define ASTR 40

__global__ __launch_bounds__(256) void k_gemm(const float* __restrict__ x,
                                              const float* __restrict__ W) {
    __shared__ __half As[128][ASTR];   // [row][k] halves, 80B row stride
    __shared__ __half Bt[64][ASTR];    // [n][k] halves (transposed W chunk)

    const int tid = threadIdx.x;
    const int lane = tid & 31;
    const int warp = tid >> 5;
    const int rowBase = blockIdx.x * 128;
    const int r4 = lane >> 2;
    const int c4 = lane & 3;

    const int ar[4] = {(0 * 256 + tid) >> 3, (1 * 256 + tid) >> 3,
                       (2 * 256 + tid) >> 3, (3 * 256 + tid) >> 3};
    const int aq = tid & 7;
    const int br[2] = {(0 * 256 + tid) >> 4, (1 * 256 + tid) >> 4};
    const int bq = tid & 15;

    float4 ra[4], rb[2];
#pragma unroll
    for (int i = 0; i < 4; i++) {
        ra[i] = make_float4(0.f, 0.f, 0.f, 0.f);
        if (rowBase + ar[i] < NN)
            ra[i] = __ldg(reinterpret_cast<const float4*>(x + (rowBase + ar[i]) * NF) + aq);
    }
#pragma unroll
    for (int i = 0; i < 2; i++)
        rb[i] = __ldg(reinterpret_cast<const float4*>(W + br[i] * NH) + bq);

    float d[8][4];
#pragma unroll
    for (int n = 0; n < 8; n++)
#pragma unroll
        for (int i = 0; i < 4; i++) d[n][i] = 0.0f;

#pragma unroll 1
    for (int ch = 0; ch < 8; ch++) {
        // Stage A: row ar[i], halves aq*4 .. aq*4+3 (8B contiguous)
#pragma unroll
        for (int i = 0; i < 4; i++) {
            __half2* p = reinterpret_cast<__half2*>(&As[ar[i]][aq * 4]);
            p[0] = __floats2half2_rn(ra[i].x, ra[i].y);
            p[1] = __floats2half2_rn(ra[i].z, ra[i].w);
        }
        // Stage B transposed: W chunk row br[i] (k), cols bq*4..+3 (n)
#pragma unroll
        for (int i = 0; i < 2; i++) {
            Bt[bq * 4 + 0][br[i]] = __float2half_rn(rb[i].x);
            Bt[bq * 4 + 1][br[i]] = __float2half_rn(rb[i].y);
            Bt[bq * 4 + 2][br[i]] = __float2half_rn(rb[i].z);
            Bt[bq * 4 + 3][br[i]] = __float2half_rn(rb[i].w);
        }
        __syncthreads();

        if (ch < 7) {
            const int k0n = (ch + 1) * 32;
#pragma unroll
            for (int i = 0; i < 4; i++) {
                ra[i] = make_float4(0.f, 0.f, 0.f, 0.f);
                if (rowBase + ar[i] < NN)
                    ra[i] = __ldg(reinterpret_cast<const float4*>(
                                      x + (rowBase + ar[i]) * NF + k0n) + aq);
            }
#pragma unroll
            for (int i = 0; i < 2; i++)
                rb[i] = __ldg(reinterpret_cast<const float4*>(W + (k0n + br[i]) * NH) + bq);
        }

        const int wr = warp * 16;
#pragma unroll
        for (int s = 0; s < 2; s++) {
            const int kb = s * 16 + 2 * c4;
            uint32_t a0 = *reinterpret_cast<const uint32_t*>(&As[wr + r4][kb]);
            uint32_t a1 = *reinterpret_cast<const uint32_t*>(&As[wr + r4 + 8][kb]);
            uint32_t a2 = *reinterpret_cast<const uint32_t*>(&As[wr + r4][kb + 8]);
            uint32_t a3 = *reinterpret_cast<const uint32_t*>(&As[wr + r4 + 8][kb + 8]);
#pragma unroll
            for (int nb = 0; nb < 8; nb++) {
                uint32_t b0 = *reinterpret_cast<const uint32_t*>(&Bt[nb * 8 + r4][kb]);
                uint32_t b1 = *reinterpret_cast<const uint32_t*>(&Bt[nb * 8 + r4][kb + 8]);
                asm volatile(
                    "mma.sync.aligned.m16n8k16.row.col.f32.f16.f16.f32 "
                    "{%0,%1,%2,%3}, {%4,%5,%6,%7}, {%8,%9}, {%0,%1,%2,%3};"
                    : "+f"(d[nb][0]), "+f"(d[nb][1]), "+f"(d[nb][2]), "+f"(d[nb][3])
                    : "r"(a0), "r"(a1), "r"(a2), "r"(a3), "r"(b0), "r"(b1));
            }
        }
        __syncthreads();
    }

    const int wr = warp * 16;
#pragma unroll
    for (int nb = 0; nb < 8; nb++) {
        int gr = rowBase + wr + r4;
        int col = nb * 8 + 2 * c4;
        if (gr < NN) {
            __half2 h = __floats2half2_rn(d[nb][0], d[nb][1]);
            *reinterpret_cast<__half2*>(g_supH + gr * NH + col) = h;
        }
        if (gr + 8 < NN) {
            __half2 h = __floats2half2_rn(d[nb][2], d[nb][3]);
            *reinterpret_cast<__half2*>(g_supH + (gr + 8) * NH + col) = h;
        }
    }
}

// ---------------------------------------------------------------------------
// CSR binning with payload reordering, then atomic-free aggregation.
// ---------------------------------------------------------------------------
__global__ void k_hist(const int* __restrict__ row) {
    int e0 = (blockIdx.x * blockDim.x + threadIdx.x) * 4;
    if (e0 >= NE) return;
    int4 r = *reinterpret_cast<const int4*>(row + e0);
    atomicAdd(&g_cnt[r.x], 1);
    atomicAdd(&g_cnt[r.y], 1);
    atomicAdd(&g_cnt[r.z], 1);
    atomicAdd(&g_cnt[r.w], 1);
}

// Local scan per 1024-chunk; LAST arriving block also scans the 98 chunk sums.
__global__ __launch_bounds__(1024) void k_scan1() {
    __shared__ int sh[1024];
    __shared__ bool s_last;
    int g = blockIdx.x * 1024 + threadIdx.x;
    int v = g_cnt[g];
    sh[threadIdx.x] = v;
    __syncthreads();
#pragma unroll
    for (int off = 1; off < 1024; off <<= 1) {
        int t = (threadIdx.x >= off) ? sh[threadIdx.x - off] : 0;
        __syncthreads();
        sh[threadIdx.x] += t;
        __syncthreads();
    }
    g_loc[g] = sh[threadIdx.x] - v;               // local exclusive
    if (threadIdx.x == 1023) g_bsum[blockIdx.x] = sh[1023];
    __syncthreads();
    if (threadIdx.x == 0) {
        __threadfence();
        unsigned int prev = atomicAdd(&g_arrive2, 1u);
        s_last = (prev == NCH - 1);
    }
    __syncthreads();
    if (s_last) {
        if (threadIdx.x < 128) {
            int i = threadIdx.x;
            int bv = (i < NCH) ? g_bsum[i] : 0;
            sh[i] = bv;
            __syncwarp();
        }
        __syncthreads();
        if (threadIdx.x < 128) {
            int i = threadIdx.x;
#pragma unroll
            for (int off = 1; off < 128; off <<= 1) {
                int t = (i >= off) ? sh[i - off] : 0;
                __syncthreads();
                sh[i] += t;
                __syncthreads();
            }
            if (i < NCH) g_bbase[i] = sh[i] - ((i < NCH) ? g_bsum[i] : 0);
            if (i == 0) g_arrive2 = 0u;
        }
    }
}

// Fill: bucket (col, ew) payload by dest row, 4 edges/thread (MLP on atomics).
__global__ void k_fill(const int* __restrict__ row, const int* __restrict__ col,
                       const float* __restrict__ ew) {
    int e0 = (blockIdx.x * blockDim.x + threadIdx.x) * 4;
    if (e0 >= NE) return;
    int4 r = *reinterpret_cast<const int4*>(row + e0);
    int4 c = *reinterpret_cast<const int4*>(col + e0);
    float4 w = *reinterpret_cast<const float4*>(ew + e0);
    int p0 = atomicAdd(&g_loc[r.x], 1) + __ldg(&g_bbase[r.x >> 10]);
    int p1 = atomicAdd(&g_loc[r.y], 1) + __ldg(&g_bbase[r.y >> 10]);
    int p2 = atomicAdd(&g_loc[r.z], 1) + __ldg(&g_bbase[r.z >> 10]);
    int p3 = atomicAdd(&g_loc[r.w], 1) + __ldg(&g_bbase[r.w >> 10]);
    g_epay[p0] = make_int2(c.x, __float_as_int(w.x));
    g_epay[p1] = make_int2(c.y, __float_as_int(w.y));
    g_epay[p2] = make_int2(c.z, __float_as_int(w.z));
    g_epay[p3] = make_int2(c.w, __float_as_int(w.w));
}

// 8 threads per row (fp16 support: 128B row = 8 x LDG.128); register acc; 1 store.
__global__ __launch_bounds__(256) void k_agg(const int* dummy) {
    int t = blockIdx.x * blockDim.x + threadIdx.x;
    int r = t >> 3;
    if (r >= NN) return;
    int l = t & 7;
    int end = __ldg(&g_loc[r]) + __ldg(&g_bbase[r >> 10]);
    int start = (r == 0) ? 0 : (__ldg(&g_loc[r - 1]) + __ldg(&g_bbase[(r - 1) >> 10]));
    const float4* sup4 = reinterpret_cast<const float4*>(g_supH);

    float2 acc[4];
#pragma unroll
    for (int j = 0; j < 4; j++) acc[j] = make_float2(0.f, 0.f);

    int2 p = (start < end) ? __ldg(&g_epay[start]) : make_int2(0, 0);
    for (int e = start; e < end; e++) {
        int2 pn = (e + 1 < end) ? __ldg(&g_epay[e + 1]) : make_int2(0, 0);
        float w = __int_as_float(p.y);
        float4 raw = __ldg(sup4 + p.x * 8 + l);
        const __half2* h = reinterpret_cast<const __half2*>(&raw);
#pragma unroll
        for (int j = 0; j < 4; j++) {
            float2 f = __half22float2(h[j]);
            acc[j].x = fmaf(w, f.x, acc[j].x);
            acc[j].y = fmaf(w, f.y, acc[j].y);
        }
        p = pn;
    }
    float* dst = g_agg + r * 64 + l * 8;
    *reinterpret_cast<float4*>(dst) = make_float4(acc[0].x, acc[0].y, acc[1].x, acc[1].y);
    *reinterpret_cast<float4*>(dst + 4) = make_float4(acc[2].x, acc[2].y, acc[3].x, acc[3].y);
}

// ---------------------------------------------------------------------------
// BN column stats (float4, high MLP) + fused finalize in the last block.
// ---------------------------------------------------------------------------
#define NSTAT_BLK 1184

__global__ __launch_bounds__(256) void k_colstats(const float* __restrict__ gamma,
                                                  const float* __restrict__ beta) {
    int j4 = threadIdx.x & 15;
    int grp = threadIdx.x >> 4;
    float4 s = make_float4(0.f, 0.f, 0.f, 0.f);
    float4 q = make_float4(0.f, 0.f, 0.f, 0.f);
    for (int r = blockIdx.x * 16 + grp; r < NN; r += NSTAT_BLK * 16) {
        float4 v = *reinterpret_cast<const float4*>(g_agg + r * 64 + j4 * 4);
        s.x += v.x; s.y += v.y; s.z += v.z; s.w += v.w;
        q.x = fmaf(v.x, v.x, q.x); q.y = fmaf(v.y, v.y, q.y);
        q.z = fmaf(v.z, v.z, q.z); q.w = fmaf(v.w, v.w, q.w);
    }
    __shared__ float ss[16][68], sq[16][68];
    __shared__ bool s_last;
    *reinterpret_cast<float4*>(&ss[grp][j4 * 4]) = s;
    *reinterpret_cast<float4*>(&sq[grp][j4 * 4]) = q;
    __syncthreads();
    if (threadIdx.x < 64) {
        int j = threadIdx.x;
        float S = 0.f, Q = 0.f;
#pragma unroll
        for (int g = 0; g < 16; g++) { S += ss[g][j]; Q += sq[g][j]; }
        atomicAdd(&g_sum[j], (double)S);
        atomicAdd(&g_sumsq[j], (double)Q);
    }
    __syncthreads();
    if (threadIdx.x == 0) {
        __threadfence();
        unsigned int prev = atomicAdd(&g_arrive, 1u);
        s_last = (prev == NSTAT_BLK - 1);
    }
    __syncthreads();
    if (s_last) {
        if (threadIdx.x < NH) {
            int j = threadIdx.x;
            double mean = g_sum[j] / (double)NN;
            double var = g_sumsq[j] / (double)NN - mean * mean;
            float sc = (float)((double)gamma[j] * rsqrt(var + 1e-5));
            g_scale[j] = sc;
            g_shift[j] = beta[j] - (float)mean * sc;
            g_sum[j] = 0.0;
            g_sumsq[j] = 0.0;
        }
        if (threadIdx.x == 64) g_arrive = 0u;
    }
}

// ---------------------------------------------------------------------------
// Epilogue: BN affine + ReLU + JAX threefry dropout (partitionable layout).
// 16 elements / thread (4 float4 chunks, stride 1024). Also re-zeroes g_cnt.
// ---------------------------------------------------------------------------
#define TFR4(rot)                                                   \
    _Pragma("unroll")                                               \
    for (int t = 0; t < 4; t++) {                                   \
        x0[t] += x1[t];                                             \
        x1[t] = __funnelshift_l(x1[t], x1[t], (rot));               \
        x1[t] ^= x0[t];                                             \
    }
#define TFK4(ka, kb, rconst)                                        \
    _Pragma("unroll")                                               \
    for (int t = 0; t < 4; t++) {                                   \
        x0[t] += (ka);                                              \
        x1[t] += (kb) + (rconst);                                   \
    }

__device__ __forceinline__ void tf_bits4(uint32_t base, uint32_t* bits) {
    const uint32_t ks0 = 0u, ks1 = 42u, ks2 = 0x1BD11BDAu ^ 42u;
    uint32_t x0[4], x1[4];
#pragma unroll
    for (int t = 0; t < 4; t++) {
        x0[t] = ks0;
        x1[t] = (base + (uint32_t)t) + ks1;
    }
    TFR4(13) TFR4(15) TFR4(26) TFR4(6)
    TFK4(ks1, ks2, 1u)
    TFR4(17) TFR4(29) TFR4(16) TFR4(24)
    TFK4(ks2, ks0, 2u)
    TFR4(13) TFR4(15) TFR4(26) TFR4(6)
    TFK4(ks0, ks1, 3u)
    TFR4(17) TFR4(29) TFR4(16) TFR4(24)
    TFK4(ks1, ks2, 4u)
    TFR4(13) TFR4(15) TFR4(26) TFR4(6)
    TFK4(ks2, ks0, 5u)
#pragma unroll
    for (int t = 0; t < 4; t++) bits[t] = x0[t] ^ x1[t];
}

__global__ __launch_bounds__(256) void k_out(float* __restrict__ out) {
    int gt = blockIdx.x * 256 + threadIdx.x;
    if (gt < NCNT) g_cnt[gt] = 0;

    const int blockBase = blockIdx.x * 4096;
    const int base0 = blockBase + threadIdx.x * 4;

    float4 v[4];
    bool ok[4];
#pragma unroll
    for (int c = 0; c < 4; c++) {
        int idx = base0 + c * 1024;
        ok[c] = idx < NHTOT;
        if (ok[c]) v[c] = *reinterpret_cast<const float4*>(g_agg + idx);
    }

    const int j = base0 & 63;
    float4 sc = *reinterpret_cast<const float4*>(g_scale + j);
    float4 sh = *reinterpret_cast<const float4*>(g_shift + j);
    const float scs[4] = {sc.x, sc.y, sc.z, sc.w};
    const float shs[4] = {sh.x, sh.y, sh.z, sh.w};
    const float inv_keep = 1.0f / 0.7f;

#pragma unroll
    for (int c = 0; c < 4; c++) {
        if (!ok[c]) continue;
        int idx = base0 + c * 1024;
        uint32_t bits[4];
        tf_bits4((uint32_t)idx, bits);
        float vals[4] = {v[c].x, v[c].y, v[c].z, v[c].w};
        float res[4];
#pragma unroll
        for (int t = 0; t < 4; t++) {
            float u = __uint_as_float((bits[t] >> 9) | 0x3f800000u) - 1.0f;
            float h = fmaxf(fmaf(vals[t], scs[t], shs[t]), 0.0f);
            res[t] = (u < 0.7f) ? h * inv_keep : 0.0f;
        }
        *reinterpret_cast<float4*>(out + idx) =
            make_float4(res[0], res[1], res[2], res[3]);
    }
}

// ---------------------------------------------------------------------------
extern "C" void kernel_launch(void* const* d_in, const int* in_sizes, int n_in,
                              void* d_out, int out_size) {
    const float* x     = (const float*)d_in[0];
    const int*   row   = (const int*)d_in[1];
    const int*   col   = (const int*)d_in[2];
    const float* ew    = (const float*)d_in[3];
    const float* W     = (const float*)d_in[4];
    const float* gamma = (const float*)d_in[6];
    const float* beta  = (const float*)d_in[7];
    float* out = (float*)d_out;

    static cudaStream_t s2 = nullptr;
    static cudaEvent_t evFork = nullptr, evJoin = nullptr;
    if (s2 == nullptr) {
        cudaStreamCreateWithFlags(&s2, cudaStreamNonBlocking);
        cudaEventCreateWithFlags(&evFork, cudaEventDisableTiming);
        cudaEventCreateWithFlags(&evJoin, cudaEventDisableTiming);
    }

    cudaEventRecord(evFork, 0);
    cudaStreamWaitEvent(s2, evFork, 0);

    k_hist<<<(NE / 4 + 255) / 256, 256, 0, s2>>>(row);
    k_scan1<<<NCH, 1024, 0, s2>>>();
    k_fill<<<(NE / 4 + 255) / 256, 256, 0, s2>>>(row, col, ew);
    cudaEventRecord(evJoin, s2);

    k_gemm<<<(NN + 127) / 128, 256>>>(x, W);

    cudaStreamWaitEvent(0, evJoin, 0);
    k_agg<<<(NN * 8 + 255) / 256, 256>>>(nullptr);
    k_colstats<<<NSTAT_BLK, 256>>>(gamma, beta);
    k_out<<<(NHTOT + 4095) / 4096, 256>>>(out);
}